// round 8
// baseline (speedup 1.0000x reference)
#include <cuda_runtime.h>
#include <cuda_bf16.h>

// Problem: B=64, L=1024, D=1280
//   pool_len = lengths + 2
//   emb[b,d]  = mean over l < pool_len of prev[b,l,d]
//   x         = relu(emb @ dense_w + dense_b)        [64,1280]
//   out       = x @ cls_w + cls_b                    [64,1]
//
// Single persistent kernel, 4 phases separated by device-wide barriers.
// Grid = 296 blocks (2 per SM on 148-SM sm_103a, all co-resident) x 320 thr.

#define Bq   64
#define Lq   1024
#define Dq   1280
#define D4   320             // float4 per row
#define NSEG 16
#define SEGR 64              // rows per pool segment

#define KS   4               // GEMM k-splits
#define KCH  320             // k per split
#define KC   64              // k staged per smem chunk
#define JT   16              // j tile
#define NJ   80              // Dq / JT

#define NB       296         // persistent blocks (2/SM x 148)
#define NTHREADS 320

// scratch (allocation-free: __device__ globals; fully overwritten every run)
__device__ float g_part [Bq * NSEG * Dq];   // pool partial sums (5.24 MB)
__device__ float g_emb  [Bq * Dq];          // pooled embedding
__device__ float g_xpart[KS * Bq * Dq];     // GEMM k-partials   (1.31 MB)

// barrier state: count returns to 0 after each barrier; phase only grows
// (monotonic generation counter -> safe across graph replays, no init needed)
__device__ unsigned g_bar_count = 0;
__device__ unsigned g_bar_phase = 0;

__device__ __forceinline__ void grid_barrier()
{
    __syncthreads();
    if (threadIdx.x == 0) {
        __threadfence();  // publish this block's writes (cumulative w/ syncthreads)
        unsigned ph = *(volatile unsigned*)&g_bar_phase;
        __threadfence();  // order phase read before count increment
        if (atomicAdd(&g_bar_count, 1u) == NB - 1u) {
            *(volatile unsigned*)&g_bar_count = 0u;   // no one touches count
            __threadfence();                           // until phase bumps
            atomicAdd(&g_bar_phase, 1u);               // release
        } else {
            while (*(volatile unsigned*)&g_bar_phase == ph) {
                __nanosleep(64);
            }
        }
        __threadfence();  // acquire released data
    }
    __syncthreads();
}

__global__ void __launch_bounds__(NTHREADS, 2) mega_kernel(
    const float* __restrict__ prev,
    const int*   __restrict__ lengths,
    const float* __restrict__ W,
    const float* __restrict__ dense_b,
    const float* __restrict__ cls_w,
    const float* __restrict__ cls_b,
    float*       __restrict__ out)
{
    const int bid = blockIdx.x;
    const int tid = threadIdx.x;

    // GEMM staging (pitch 68 floats keeps float4 rows 16B-aligned)
    __shared__ __align__(16) float sE[KC][68];   // 17.4 KB
    __shared__ __align__(16) float sW[KC][JT];   //  4.0 KB
    __shared__ float red[16];

    // ===================== Phase 1: ragged partial pool =====================
    // tasks: 1024 (b, seg), seg-major so each block mixes full/empty segments
    for (int t = bid; t < Bq * NSEG; t += NB) {
        const int b   = t & 63;
        const int seg = t >> 6;

        const int pl = lengths[b] + 2;              // pool_len in [2, 1023]
        const int l0 = seg * SEGR;
        const int n  = min(SEGR, pl - l0);

        float4 a0 = make_float4(0.f, 0.f, 0.f, 0.f);
        float4 a1 = a0, a2 = a0, a3 = a0;

        if (n > 0) {
            const float4* __restrict__ p =
                reinterpret_cast<const float4*>(prev) + ((size_t)b * Lq + l0) * D4 + tid;
            int l = 0;
            for (; l + 8 <= n; l += 8) {
                float4 v0 = p[(size_t)(l + 0) * D4];
                float4 v1 = p[(size_t)(l + 1) * D4];
                float4 v2 = p[(size_t)(l + 2) * D4];
                float4 v3 = p[(size_t)(l + 3) * D4];
                float4 v4 = p[(size_t)(l + 4) * D4];
                float4 v5 = p[(size_t)(l + 5) * D4];
                float4 v6 = p[(size_t)(l + 6) * D4];
                float4 v7 = p[(size_t)(l + 7) * D4];
                a0.x += v0.x; a0.y += v0.y; a0.z += v0.z; a0.w += v0.w;
                a1.x += v1.x; a1.y += v1.y; a1.z += v1.z; a1.w += v1.w;
                a2.x += v2.x; a2.y += v2.y; a2.z += v2.z; a2.w += v2.w;
                a3.x += v3.x; a3.y += v3.y; a3.z += v3.z; a3.w += v3.w;
                a0.x += v4.x; a0.y += v4.y; a0.z += v4.z; a0.w += v4.w;
                a1.x += v5.x; a1.y += v5.y; a1.z += v5.z; a1.w += v5.w;
                a2.x += v6.x; a2.y += v6.y; a2.z += v6.z; a2.w += v6.w;
                a3.x += v7.x; a3.y += v7.y; a3.z += v7.z; a3.w += v7.w;
            }
            for (; l < n; ++l) {
                float4 v = p[(size_t)l * D4];
                a0.x += v.x; a0.y += v.y; a0.z += v.z; a0.w += v.w;
            }
        }
        float4 s;
        s.x = (a0.x + a1.x) + (a2.x + a3.x);
        s.y = (a0.y + a1.y) + (a2.y + a3.y);
        s.z = (a0.z + a1.z) + (a2.z + a3.z);
        s.w = (a0.w + a1.w) + (a2.w + a3.w);
        reinterpret_cast<float4*>(g_part)[((size_t)b * NSEG + seg) * D4 + tid] = s;
    }

    grid_barrier();

    // ===================== Phase 2: reduce + scale =====================
    for (int b = bid; b < Bq; b += NB) {
        const float4* gp = reinterpret_cast<const float4*>(g_part);
        float4 s = make_float4(0.f, 0.f, 0.f, 0.f);
#pragma unroll
        for (int seg = 0; seg < NSEG; ++seg) {
            float4 v = gp[((size_t)b * NSEG + seg) * D4 + tid];
            s.x += v.x; s.y += v.y; s.z += v.z; s.w += v.w;
        }
        const float inv = 1.0f / (float)(lengths[b] + 2);
        s.x *= inv; s.y *= inv; s.z *= inv; s.w *= inv;
        reinterpret_cast<float4*>(g_emb)[(size_t)b * D4 + tid] = s;
    }

    grid_barrier();

    // ===================== Phase 3: k-split GEMM =====================
    // tasks: 320 (ky, jx). 256 compute threads: thread = (bq 0..15, j 0..15),
    // owns 4 consecutive b for one j. Staging uses all 320 threads.
    for (int t = bid; t < NJ * KS; t += NB) {
        const int ky = t / NJ;
        const int jx = t % NJ;
        const int j0 = jx * JT;
        const int k0 = ky * KCH;

        float acc0 = 0.f, acc1 = 0.f, acc2 = 0.f, acc3 = 0.f;
        const int j  = tid & 15;
        const int bq = tid >> 4;

        for (int c = 0; c < KCH; c += KC) {
            __syncthreads();
            // stage emb^T: consecutive tid -> consecutive kk (coalesced)
            for (int i = tid; i < KC * Bq; i += NTHREADS) {
                int kk = i & (KC - 1);
                int b  = i >> 6;
                sE[kk][b] = g_emb[(size_t)b * Dq + k0 + c + kk];
            }
            for (int i = tid; i < KC * JT; i += NTHREADS) {
                int kk = i >> 4;
                int jj = i & 15;
                sW[kk][jj] = W[(size_t)(k0 + c + kk) * Dq + j0 + jj];
            }
            __syncthreads();

            if (tid < 256) {
#pragma unroll 8
                for (int kk = 0; kk < KC; ++kk) {
                    float4 e = *reinterpret_cast<const float4*>(&sE[kk][4 * bq]);
                    float  w = sW[kk][j];
                    acc0 += e.x * w;
                    acc1 += e.y * w;
                    acc2 += e.z * w;
                    acc3 += e.w * w;
                }
            }
        }
        if (tid < 256) {
            float* dst = &g_xpart[((size_t)ky * Bq + 4 * bq) * Dq + j0 + j];
            dst[0]          = acc0;
            dst[Dq]         = acc1;
            dst[2 * Dq]     = acc2;
            dst[3 * Dq]     = acc3;
        }
    }

    grid_barrier();

    // ===================== Phase 4: final (one block per b, no atomics) ====
    for (int b = bid; b < Bq; b += NB) {
        const float4* xp = reinterpret_cast<const float4*>(g_xpart);
        float4 s = reinterpret_cast<const float4*>(dense_b)[tid];
#pragma unroll
        for (int ks = 0; ks < KS; ++ks) {
            float4 v = xp[((size_t)ks * Bq + b) * D4 + tid];
            s.x += v.x; s.y += v.y; s.z += v.z; s.w += v.w;
        }
        s.x = fmaxf(s.x, 0.f); s.y = fmaxf(s.y, 0.f);
        s.z = fmaxf(s.z, 0.f); s.w = fmaxf(s.w, 0.f);

        float4 w = reinterpret_cast<const float4*>(cls_w)[tid];
        float part = s.x * w.x + s.y * w.y + s.z * w.z + s.w * w.w;

#pragma unroll
        for (int o = 16; o > 0; o >>= 1)
            part += __shfl_down_sync(0xffffffffu, part, o);
        if ((tid & 31) == 0) red[tid >> 5] = part;
        __syncthreads();
        if (tid == 0) {
            float tot = 0.f;
#pragma unroll
            for (int i = 0; i < 10; ++i) tot += red[i];
            out[b] = tot + cls_b[0];
        }
        __syncthreads();   // protect red[] reuse across b iterations
    }
}

// ---------------------------------------------------------------------------
extern "C" void kernel_launch(void* const* d_in, const int* in_sizes, int n_in,
                              void* d_out, int out_size)
{
    const float* prev    = (const float*)d_in[0];
    const int*   lengths = (const int*)  d_in[1];
    const float* dense_w = (const float*)d_in[2];
    const float* dense_b = (const float*)d_in[3];
    const float* cls_w   = (const float*)d_in[4];
    const float* cls_b   = (const float*)d_in[5];
    float*       out     = (float*)d_out;

    mega_kernel<<<NB, NTHREADS>>>(prev, lengths, dense_w, dense_b,
                                  cls_w, cls_b, out);
}